// round 6
// baseline (speedup 1.0000x reference)
#include <cuda_runtime.h>
#include <cstdint>

#define BATCH  64
#define TSTEPS 1024
#define DDIM   512
#define FDIM   512

#define CLUSTER 8
#define NB      4          // batches per cluster
#define FCHUNK  64         // features per CTA (512/8)
#define NCLUST  (BATCH / NB)       // 16
#define NCTA2   (NCLUST * CLUSTER) // 128

// ----------------------------------------------------------------------------
// Phase 1: x_proj = inputs @ W_ih + bias   (M=65536, N=512, K=512, fp32)
// Written into d_out; phase 2 reads it back and overwrites with h.
// ----------------------------------------------------------------------------
__global__ __launch_bounds__(256) void xproj_kernel(
    const float* __restrict__ A,     // [65536, 512]
    const float* __restrict__ W,     // [512, 512]
    const float* __restrict__ bias,  // [512]
    float* __restrict__ C)           // [65536, 512]
{
    __shared__ float As[8][128];  // transposed A tile: As[k][m]
    __shared__ float Bs[8][128];  // Bs[k][n]

    const int tid = threadIdx.x;
    const int m0 = blockIdx.y * 128;
    const int n0 = blockIdx.x * 128;
    const int tx = tid & 15;     // 16 threads in n
    const int ty = tid >> 4;     // 16 threads in m
    const int arow = tid >> 1;          // 0..127
    const int ac4  = (tid & 1) << 2;    // 0 or 4
    const int brow = tid >> 5;          // 0..7
    const int bc4  = (tid & 31) << 2;   // 0..124

    float acc[8][8];
#pragma unroll
    for (int i = 0; i < 8; i++)
#pragma unroll
        for (int j = 0; j < 8; j++) acc[i][j] = 0.f;

    for (int k0 = 0; k0 < DDIM; k0 += 8) {
        const float4 av = *(const float4*)&A[(m0 + arow) * DDIM + k0 + ac4];
        const float4 bv = *(const float4*)&W[(k0 + brow) * FDIM + n0 + bc4];
        __syncthreads();
        As[ac4 + 0][arow] = av.x;
        As[ac4 + 1][arow] = av.y;
        As[ac4 + 2][arow] = av.z;
        As[ac4 + 3][arow] = av.w;
        *(float4*)&Bs[brow][bc4] = bv;
        __syncthreads();
#pragma unroll
        for (int k = 0; k < 8; k++) {
            float a[8], b[8];
            *(float4*)&a[0] = *(const float4*)&As[k][ty * 8];
            *(float4*)&a[4] = *(const float4*)&As[k][ty * 8 + 4];
            *(float4*)&b[0] = *(const float4*)&Bs[k][tx * 8];
            *(float4*)&b[4] = *(const float4*)&Bs[k][tx * 8 + 4];
#pragma unroll
            for (int i = 0; i < 8; i++)
#pragma unroll
                for (int j = 0; j < 8; j++)
                    acc[i][j] = fmaf(a[i], b[j], acc[i][j]);
        }
    }

    const int nb = n0 + tx * 8;
    float bv8[8];
#pragma unroll
    for (int j = 0; j < 8; j++) bv8[j] = bias[nb + j];

#pragma unroll
    for (int i = 0; i < 8; i++) {
        float* cp = C + (m0 + ty * 8 + i) * FDIM + nb;
        float4 v0 = make_float4(acc[i][0] + bv8[0], acc[i][1] + bv8[1],
                                acc[i][2] + bv8[2], acc[i][3] + bv8[3]);
        float4 v1 = make_float4(acc[i][4] + bv8[4], acc[i][5] + bv8[5],
                                acc[i][6] + bv8[6], acc[i][7] + bv8[7]);
        *(float4*)cp = v0;
        *(float4*)(cp + 4) = v1;
    }
}

// ----------------------------------------------------------------------------
// Phase 2: sequential scan. Cluster of 8 CTAs per batch-group (4 batches).
// Each CTA: W_hh slice [512, 64] in SMEM; per step computes its F-chunk of
// h_next for the 4 batches, broadcasts via DSMEM, one cluster barrier per step.
// ----------------------------------------------------------------------------

// dynamic SMEM layout (floats):
//   Ws  [512*64]          = 32768   W_hh slice, Ws[k*64 + f]
//   H   [2][NB][512]      = 4096    double-buffered hidden state
//   RED [16][256]         = 4096    K-split partial sums
#define SM_WS   0
#define SM_H    (512 * FCHUNK)
#define SM_RED  (SM_H + 2 * NB * 512)
#define SM_FLOATS (SM_RED + 16 * 256)   // 40960 floats = 163840 B

__device__ __forceinline__ void cluster_sync_() {
    asm volatile("barrier.cluster.arrive.aligned;" ::: "memory");
    asm volatile("barrier.cluster.wait.aligned;" ::: "memory");
}

__device__ __forceinline__ float f4get(const float4 v, int j) {
    return j == 0 ? v.x : (j == 1 ? v.y : (j == 2 ? v.z : v.w));
}

extern __shared__ float smem2[];

__global__ __launch_bounds__(256, 1) __cluster_dims__(CLUSTER, 1, 1)
void rnn_scan_kernel(const float* __restrict__ w_hh,  // [512, 512]
                     float* __restrict__ xo)          // [B, T, F]: xp in, h out
{
    float* Ws  = smem2 + SM_WS;
    float* H   = smem2 + SM_H;
    float* RED = smem2 + SM_RED;

    const int tid  = threadIdx.x;
    const int rank = blockIdx.x % CLUSTER;   // cluster rank (x-major)
    const int bg   = blockIdx.x / CLUSTER;   // batch group 0..15
    const int f0   = rank * FCHUNK;

    // Load W_hh slice: Ws[k*64 + f] = w_hh[k*512 + f0 + f]
    for (int i = tid; i < 512 * FCHUNK; i += 256) {
        const int k = i >> 6;
        const int f = i & 63;
        Ws[i] = w_hh[k * FDIM + f0 + f];
    }
    // h(-1) = 0 lives in buffer 1 (step 0 reads buffer 1-p with p=0)
    for (int i = tid; i < NB * 512; i += 256) H[NB * 512 + i] = 0.f;
    __syncthreads();
    cluster_sync_();

    // compute-role indices
    const int f4    = tid & 15;   // feature quad 0..15
    const int ks    = tid >> 4;   // K slice 0..15
    const int kbase = ks * 32;
    // output-role indices
    const int ob = tid >> 6;      // 0..3
    const int of = tid & 63;      // 0..63
    const int bglob = bg * NB + ob;
    float* xo_ptr = xo + (size_t)bglob * TSTEPS * FDIM + f0 + of;

    // SMEM byte address of H for DSMEM broadcast
    uint32_t h_u32;
    {
        uint32_t s;
        asm("{ .reg .u64 t; cvta.to.shared.u64 t, %1; cvt.u32.u64 %0, t; }"
            : "=r"(s) : "l"(smem2));
        h_u32 = s + (uint32_t)(SM_H * 4);
    }

#pragma unroll 1
    for (int t = 0; t < TSTEPS; t++) {
        const int p = t & 1;
        const float xpv = xo_ptr[t * FDIM];     // issued early, hidden by K-loop
        const float* hp = H + (1 - p) * NB * 512;  // hp[b*512 + k]

        float acc[NB][4];
#pragma unroll
        for (int b = 0; b < NB; b++)
#pragma unroll
            for (int j = 0; j < 4; j++) acc[b][j] = 0.f;

#pragma unroll
        for (int kk = 0; kk < 32; kk += 4) {
            const int k = kbase + kk;
            float4 hq[NB];
#pragma unroll
            for (int b = 0; b < NB; b++)
                hq[b] = *(const float4*)&hp[b * 512 + k];
#pragma unroll
            for (int j = 0; j < 4; j++) {
                const float4 w = *(const float4*)&Ws[(k + j) * FCHUNK + (f4 << 2)];
#pragma unroll
                for (int b = 0; b < NB; b++) {
                    const float hb = f4get(hq[b], j);
                    acc[b][0] = fmaf(hb, w.x, acc[b][0]);
                    acc[b][1] = fmaf(hb, w.y, acc[b][1]);
                    acc[b][2] = fmaf(hb, w.z, acc[b][2]);
                    acc[b][3] = fmaf(hb, w.w, acc[b][3]);
                }
            }
        }

        // write K-split partials: RED[ks][b*64 + f4*4 + j]
#pragma unroll
        for (int b = 0; b < NB; b++) {
            *(float4*)&RED[ks * 256 + b * 64 + (f4 << 2)] =
                make_float4(acc[b][0], acc[b][1], acc[b][2], acc[b][3]);
        }
        __syncthreads();

        // reduce 16 partials for output (ob, of)
        float z = xpv;
#pragma unroll
        for (int s = 0; s < 16; s++) z += RED[s * 256 + tid];
        const float hv = tanhf(z);

        // write output (overwrites the xp we just consumed)
        xo_ptr[t * FDIM] = hv;

        // broadcast h into every cluster CTA's H[p][ob][f0+of]
        const uint32_t laddr =
            h_u32 + (uint32_t)(((p * NB + ob) * 512 + f0 + of) * 4);
#pragma unroll
        for (int r = 0; r < CLUSTER; r++) {
            uint32_t raddr;
            asm("mapa.shared::cluster.u32 %0, %1, %2;"
                : "=r"(raddr) : "r"(laddr), "r"(r));
            asm volatile("st.shared::cluster.f32 [%0], %1;"
                         :: "r"(raddr), "f"(hv) : "memory");
        }
        cluster_sync_();   // release/acquire: h(p) visible cluster-wide
    }
}

// ----------------------------------------------------------------------------
extern "C" void kernel_launch(void* const* d_in, const int* in_sizes, int n_in,
                              void* d_out, int out_size)
{
    const float* inputs = (const float*)d_in[0];  // [64,1024,512]
    const float* w_ih   = (const float*)d_in[1];  // [512,512]
    const float* w_hh   = (const float*)d_in[2];  // [512,512]
    const float* bias   = (const float*)d_in[3];  // [512]
    float* out = (float*)d_out;                   // [64,1024,512]

    cudaFuncSetAttribute(rnn_scan_kernel,
                         cudaFuncAttributeMaxDynamicSharedMemorySize,
                         SM_FLOATS * 4);

    // Phase 1: x_proj into d_out
    {
        dim3 grid(FDIM / 128, (BATCH * TSTEPS) / 128);  // (4, 512)
        xproj_kernel<<<grid, 256>>>(inputs, w_ih, bias, out);
    }
    // Phase 2: sequential scan (clustered persistent kernel)
    {
        rnn_scan_kernel<<<NCTA2, 256, SM_FLOATS * 4>>>(w_hh, out);
    }
}